// round 3
// baseline (speedup 1.0000x reference)
#include <cuda_runtime.h>
#include <cstdint>

// FastRP link prediction:
//   w = softmax(feature_weights over K)           [P=4, K=3]
//   emb[n] = sum_{p,k} w[p,k] * feats[p,k,n,:]    D=64
//   out[e] = sigmoid(intercept - ||emb[i]-emb[j]||^2 / D)
//
// Strategy: direct per-edge gather (no emb materialization).
// One warp per edge; lanes 0-15 = node i, lanes 16-31 = node j,
// each lane owns 4 dims (float4). 12 independent LDG.128 per lane.
// NOTE: harness canonicalizes int64 indices to int32 -> cast to const int*.

#define P_PATHS 4
#define K_POWERS 3
#define PK 12
#define DIM 64

__global__ __launch_bounds__(256) void fastrp_edge_kernel(
    const float* __restrict__ feats,      // [PK, N, 64]
    const float* __restrict__ fw,         // [P, K] = 12 floats
    const float* __restrict__ intercept,  // scalar
    const int* __restrict__ idx_i,        // [E]
    const int* __restrict__ idx_j,        // [E]
    float* __restrict__ out,              // [E]
    int E, int N)
{
    const int gwarp = (blockIdx.x * blockDim.x + threadIdx.x) >> 5;
    const int lane  = threadIdx.x & 31;
    if (gwarp >= E) return;

    // ---- softmax weights over K per path (12 values, computed per-thread) ----
    float w[PK];
    #pragma unroll
    for (int p = 0; p < P_PATHS; p++) {
        float a = __ldg(fw + p * K_POWERS + 0);
        float b = __ldg(fw + p * K_POWERS + 1);
        float c = __ldg(fw + p * K_POWERS + 2);
        float m = fmaxf(a, fmaxf(b, c));
        float ea = __expf(a - m);
        float eb = __expf(b - m);
        float ec = __expf(c - m);
        float inv = 1.0f / (ea + eb + ec);
        w[p * K_POWERS + 0] = ea * inv;
        w[p * K_POWERS + 1] = eb * inv;
        w[p * K_POWERS + 2] = ec * inv;
    }

    // ---- pick node for this half-warp ----
    const int ni = __ldg(idx_i + gwarp);
    const int nj = __ldg(idx_j + gwarp);
    const long long node = (lane < 16) ? (long long)ni : (long long)nj;
    const int d4 = lane & 15;  // which float4 of the 16 making up 64 dims

    const float4* __restrict__ f4 = (const float4*)feats;
    // float4 index for slice pk: (pk*N + node)*16 + d4
    const long long nodebase = node * 16 + d4;
    const long long stride16 = (long long)N * 16;

    float ax = 0.f, ay = 0.f, az = 0.f, aw = 0.f;
    #pragma unroll
    for (int pk = 0; pk < PK; pk++) {
        float4 v = __ldg(f4 + (long long)pk * stride16 + nodebase);
        ax = fmaf(w[pk], v.x, ax);
        ay = fmaf(w[pk], v.y, ay);
        az = fmaf(w[pk], v.z, az);
        aw = fmaf(w[pk], v.w, aw);
    }

    // ---- diff across the two half-warps (same dims live at lane ^ 16) ----
    const unsigned FULL = 0xffffffffu;
    float dx = ax - __shfl_xor_sync(FULL, ax, 16);
    float dy = ay - __shfl_xor_sync(FULL, ay, 16);
    float dz = az - __shfl_xor_sync(FULL, az, 16);
    float dw = aw - __shfl_xor_sync(FULL, aw, 16);
    float s = dx * dx + dy * dy + dz * dz + dw * dw;

    // ---- reduce over the 16 lanes of each half (both halves hold same |d|^2) ----
    #pragma unroll
    for (int off = 8; off >= 1; off >>= 1)
        s += __shfl_xor_sync(FULL, s, off);

    if (lane == 0) {
        float logit = __ldg(intercept) - s * (1.0f / (float)DIM);
        out[gwarp] = 1.0f / (1.0f + __expf(-logit));
    }
}

extern "C" void kernel_launch(void* const* d_in, const int* in_sizes, int n_in,
                              void* d_out, int out_size)
{
    const float* feats     = (const float*)d_in[0];
    const float* fw        = (const float*)d_in[1];
    const float* intercept = (const float*)d_in[2];
    const int*   idx_i     = (const int*)d_in[3];
    const int*   idx_j     = (const int*)d_in[4];
    float*       out       = (float*)d_out;

    const int E = in_sizes[3];
    const int N = in_sizes[0] / (PK * DIM);

    // one warp per edge, 8 warps (256 threads) per block
    const int warps_per_block = 8;
    const int blocks = (E + warps_per_block - 1) / warps_per_block;
    fastrp_edge_kernel<<<blocks, warps_per_block * 32>>>(
        feats, fw, intercept, idx_i, idx_j, out, E, N);
}